// round 11
// baseline (speedup 1.0000x reference)
#include <cuda_runtime.h>
#include <cuda_bf16.h>
#include <cstdint>
#include <cstddef>

// ---------------------------------------------------------------------------
// Problem constants
// ---------------------------------------------------------------------------
#define N_CODES 4880
#define T_STEPS 4096
#define VDIM    512
#define HD      512
#define G3      1536   // 3*HD

typedef unsigned long long ull;

// ---------------------------------------------------------------------------
// Scratch (device globals — no allocation allowed)
// ---------------------------------------------------------------------------
__device__ float g_visit[(size_t)T_STEPS * VDIM];     // 8 MB
__device__ float g_gi[(size_t)T_STEPS * G3];          // 24 MB
__device__ float g_hs[(size_t)T_STEPS * HD];          // 8 MB
__device__ float g_logits[T_STEPS];
__device__ float g_alpha[T_STEPS];
__device__ float g_part[32 * HD];

// ---------------------------------------------------------------------------
// Helpers
// ---------------------------------------------------------------------------
__device__ __forceinline__ unsigned smem_u32(const void* p) {
    unsigned a;
    asm("{ .reg .u64 t; cvta.to.shared.u64 t, %1; cvt.u32.u64 %0, t; }"
        : "=r"(a) : "l"(p));
    return a;
}
__device__ __forceinline__ unsigned mapa_u32(unsigned laddr, int rk) {
    unsigned r;
    asm("mapa.shared::cluster.u32 %0, %1, %2;" : "=r"(r) : "r"(laddr), "r"(rk));
    return r;
}
__device__ __forceinline__ ull pk2(float a, float b) {
    ull r; asm("mov.b64 %0, {%1, %2};" : "=l"(r) : "f"(a), "f"(b)); return r;
}
__device__ __forceinline__ ull pk2dup(float a) { return pk2(a, a); }
__device__ __forceinline__ void fma2(ull& d, ull a, ull b) {
    asm("fma.rn.f32x2 %0, %1, %2, %0;" : "+l"(d) : "l"(a), "l"(b));
}
__device__ __forceinline__ float2 upk2(ull v) {
    float2 r; asm("mov.b64 {%0, %1}, %2;" : "=f"(r.x), "=f"(r.y) : "l"(v));
    return r;
}
__device__ __forceinline__ float tanh_fast(float x) {
    float r; asm("tanh.approx.f32 %0, %1;" : "=f"(r) : "f"(x)); return r;
}
__device__ __forceinline__ void cluster_sync_all() {
    asm volatile("barrier.cluster.arrive.aligned;" ::: "memory");
    asm volatile("barrier.cluster.wait.aligned;" ::: "memory");
}
__device__ __forceinline__ void mbar_init(unsigned a, unsigned cnt) {
    asm volatile("mbarrier.init.shared.b64 [%0], %1;" :: "r"(a), "r"(cnt) : "memory");
}
__device__ __forceinline__ void mbar_expect(unsigned a, unsigned bytes) {
    asm volatile("mbarrier.arrive.expect_tx.shared.b64 _, [%0], %1;"
                 :: "r"(a), "r"(bytes) : "memory");
}
__device__ __forceinline__ void mbar_wait(unsigned a, unsigned parity) {
    asm volatile(
        "{\n\t.reg .pred P;\n\t"
        "LW_%=:\n\t"
        "mbarrier.try_wait.parity.acquire.cluster.shared::cta.b64 P, [%0], %1, 0x989680;\n\t"
        "@P bra.uni LD_%=;\n\t"
        "bra.uni LW_%=;\n\t"
        "LD_%=:\n\t}"
        :: "r"(a), "r"(parity) : "memory");
}
__device__ __forceinline__ void st_async_b64(unsigned ra, unsigned rb, ull val) {
    asm volatile(
        "st.async.shared::cluster.mbarrier::complete_tx::bytes.b64 [%0], %1, [%2];"
        :: "r"(ra), "l"(val), "r"(rb) : "memory");
}

// ---------------------------------------------------------------------------
// GEMM1: visit[t][d] = sum_k H[k][t] * X[k][d]
//   128x64 tile, 256 threads, 8x4 per thread (f32x2-packed along m)
// ---------------------------------------------------------------------------
__global__ void __launch_bounds__(256)
gemm1_kernel(const float* __restrict__ H, const float* __restrict__ X)
{
    __shared__ float As[16 * 128];
    __shared__ float Bs[16 * 64];
    const int tid = threadIdx.x;
    const int t0 = blockIdx.x * 128;
    const int d0 = blockIdx.y * 64;
    const int tx = tid & 15;
    const int ty = tid >> 4;

    ull acc2[4][4];
#pragma unroll
    for (int mp = 0; mp < 4; mp++)
#pragma unroll
        for (int n = 0; n < 4; n++) acc2[mp][n] = 0ull;

    for (int k0 = 0; k0 < N_CODES; k0 += 16) {
#pragma unroll
        for (int j = 0; j < 2; j++) {
            int idx = tid + (j << 8);
            int kk  = idx >> 5;
            int tt4 = (idx & 31) << 2;
            float4 v = *(const float4*)(H + (size_t)(k0 + kk) * T_STEPS + t0 + tt4);
            *(float4*)(As + (kk << 7) + tt4) = v;
        }
        {
            int kk  = tid >> 4;
            int dd4 = (tid & 15) << 2;
            float4 v = *(const float4*)(X + (size_t)(k0 + kk) * VDIM + d0 + dd4);
            *(float4*)(Bs + (kk << 6) + dd4) = v;
        }
        __syncthreads();
#pragma unroll
        for (int kk = 0; kk < 16; kk++) {
            const longlong2* ap = (const longlong2*)(As + (kk << 7) + (ty << 3));
            longlong2 a01 = ap[0];
            longlong2 a23 = ap[1];
            ull am[4] = {(ull)a01.x, (ull)a01.y, (ull)a23.x, (ull)a23.y};
            float4 b = *(const float4*)(Bs + (kk << 6) + (tx << 2));
            ull bd[4] = {pk2dup(b.x), pk2dup(b.y), pk2dup(b.z), pk2dup(b.w)};
#pragma unroll
            for (int mp = 0; mp < 4; mp++)
#pragma unroll
                for (int n = 0; n < 4; n++)
                    fma2(acc2[mp][n], am[mp], bd[n]);
        }
        __syncthreads();
    }
#pragma unroll
    for (int mp = 0; mp < 4; mp++) {
        float2 c0 = upk2(acc2[mp][0]);
        float2 c1 = upk2(acc2[mp][1]);
        float2 c2 = upk2(acc2[mp][2]);
        float2 c3 = upk2(acc2[mp][3]);
        size_t r0 = (size_t)(t0 + (ty << 3) + 2 * mp) * VDIM + d0 + (tx << 2);
        *(float4*)(g_visit + r0)        = make_float4(c0.x, c1.x, c2.x, c3.x);
        *(float4*)(g_visit + r0 + VDIM) = make_float4(c0.y, c1.y, c2.y, c3.y);
    }
}

// ---------------------------------------------------------------------------
// GEMM2: gi[t][g] = b_ih[g] + sum_d visit[t][d] * W_ih[g][d]
// ---------------------------------------------------------------------------
__global__ void __launch_bounds__(256)
gemm2_kernel(const float* __restrict__ Wih, const float* __restrict__ bih)
{
    __shared__ float As[16 * 128];
    __shared__ float Bs[16 * 64];
    const int tid = threadIdx.x;
    const int t0 = blockIdx.x * 128;
    const int g0 = blockIdx.y * 64;
    const int tx = tid & 15;
    const int ty = tid >> 4;

    ull acc2[4][4];
#pragma unroll
    for (int mp = 0; mp < 4; mp++)
#pragma unroll
        for (int n = 0; n < 4; n++) acc2[mp][n] = 0ull;

    for (int k0 = 0; k0 < VDIM; k0 += 16) {
#pragma unroll
        for (int j = 0; j < 2; j++) {
            int idx = tid + (j << 8);
            int tt  = idx >> 2;
            int kk  = (idx & 3) << 2;
            float4 v = *(const float4*)(g_visit + (size_t)(t0 + tt) * VDIM + k0 + kk);
            As[(kk + 0) * 128 + tt] = v.x;
            As[(kk + 1) * 128 + tt] = v.y;
            As[(kk + 2) * 128 + tt] = v.z;
            As[(kk + 3) * 128 + tt] = v.w;
        }
        {
            int gg = tid >> 2;
            int kk = (tid & 3) << 2;
            float4 v = *(const float4*)(Wih + (size_t)(g0 + gg) * VDIM + k0 + kk);
            Bs[(kk + 0) * 64 + gg] = v.x;
            Bs[(kk + 1) * 64 + gg] = v.y;
            Bs[(kk + 2) * 64 + gg] = v.z;
            Bs[(kk + 3) * 64 + gg] = v.w;
        }
        __syncthreads();
#pragma unroll
        for (int kk = 0; kk < 16; kk++) {
            const longlong2* ap = (const longlong2*)(As + (kk << 7) + (ty << 3));
            longlong2 a01 = ap[0];
            longlong2 a23 = ap[1];
            ull am[4] = {(ull)a01.x, (ull)a01.y, (ull)a23.x, (ull)a23.y};
            float4 b = *(const float4*)(Bs + (kk << 6) + (tx << 2));
            ull bd[4] = {pk2dup(b.x), pk2dup(b.y), pk2dup(b.z), pk2dup(b.w)};
#pragma unroll
            for (int mp = 0; mp < 4; mp++)
#pragma unroll
                for (int n = 0; n < 4; n++)
                    fma2(acc2[mp][n], am[mp], bd[n]);
        }
        __syncthreads();
    }
    float4 bv = *(const float4*)(bih + g0 + (tx << 2));
#pragma unroll
    for (int mp = 0; mp < 4; mp++) {
        float2 c0 = upk2(acc2[mp][0]);
        float2 c1 = upk2(acc2[mp][1]);
        float2 c2 = upk2(acc2[mp][2]);
        float2 c3 = upk2(acc2[mp][3]);
        size_t r0 = (size_t)(t0 + (ty << 3) + 2 * mp) * G3 + g0 + (tx << 2);
        *(float4*)(g_gi + r0)      = make_float4(c0.x + bv.x, c1.x + bv.y, c2.x + bv.z, c3.x + bv.w);
        *(float4*)(g_gi + r0 + G3) = make_float4(c0.y + bv.x, c1.y + bv.y, c2.y + bv.z, c3.y + bv.w);
    }
}

// ---------------------------------------------------------------------------
// GRU scan: 16-CTA cluster, 256 threads (8 warps), BAR-FREE loop.
// All 6 weight groups in registers. PACKED b64 fan-out: warp w's 4 hnew values
// are 16 contiguous dest bytes; lanes re-map to (rank = lane>>1, pair = lane&1)
// and each issues ONE st.async.b64 (256 tx/dest/step instead of 512).
// ---------------------------------------------------------------------------
#define SCAN_THREADS 256

__global__ void __launch_bounds__(SCAN_THREADS, 1)
scan_kernel(const float* __restrict__ Whh, const float* __restrict__ bhh)
{
    __shared__ float  hT[2 * HD];         // transposed h, 2 buffers
    __shared__ ull    mbar[2];

    const int tid  = threadIdx.x;
    const int lane = tid & 31;
    const int w    = tid >> 5;
    const int cta  = blockIdx.x;          // cluster rank
    const int c4   = lane & 15;           // h-chunk (source CTA) index
    const int rh   = lane >> 4;

    const int ui    = ((lane & 1) << 1) | rh;   // this lane's unit-low (0..3)
    const int q     = (lane >> 1) & 7;
    const int ul    = (w << 2) + ui;
    const int u_gbl = (cta << 5) + ul;

    // fan-out identity: rank rk gets pair p (units 2p, 2p+1)
    const int rk = lane >> 1;             // 0..15
    const int p  = lane & 1;              // 0..1

    // --- one-time weight staging: all 6 groups in registers ---
    ull wreg[6][16];
#pragma unroll
    for (int g = 0; g < 6; g++) {
        int grow = ((g >> 1) << 9) + (cta << 5) + (w << 2) + ((g & 1) << 1) + rh;
        const ull* src = (const ull*)(Whh + (size_t)grow * HD + (c4 << 5));
#pragma unroll
        for (int k = 0; k < 16; k++) wreg[g][k] = src[k];
    }
    const float br = bhh[u_gbl];
    const float bz = bhh[HD + u_gbl];
    const float bn = bhh[2 * HD + u_gbl];

    for (int i = tid; i < HD; i += SCAN_THREADS) hT[i] = 0.0f;
    if (tid == 0) { mbar_init(smem_u32(&mbar[0]), 1); mbar_init(smem_u32(&mbar[1]), 1); }
    __syncthreads();
    cluster_sync_all();

    // precompute remote addresses: one b64 dest per buffer
    // dest float offset (within dest CTA): (w<<6) + (cta<<2) + 2p  (8B aligned)
    const int hoffb = ((ul >> 2) << 6) + (cta << 2) + (ul & 3);   // own-unit offset
    unsigned rdata[2], rbar[2];
#pragma unroll
    for (int b = 0; b < 2; b++) {
        unsigned ld = smem_u32(&hT[(b << 9) + (w << 6) + (cta << 2) + (p << 1)]);
        unsigned lm = smem_u32(&mbar[b]);
        rdata[b] = mapa_u32(ld, rk);
        rbar[b]  = mapa_u32(lm, rk);
    }

    // gi preload for t=0; carried pointer
    const float* gp_cur = g_gi + u_gbl;
    float gir = __ldg(gp_cur);
    float giz = __ldg(gp_cur + HD);
    float gin = __ldg(gp_cur + 2 * HD);

    int ph0 = 0, ph1 = 0;
    const bool b0 = (lane & 1);
    for (int t = 0; t < T_STEPS; t++) {
        const int cb = t & 1;
        const int nb = cb ^ 1;

        if (tid == 0) mbar_expect(smem_u32(&mbar[nb]), 2048u);

        // prefetch gi for t+1 (carried pointer)
        const float* gp_n = (t + 1 < T_STEPS) ? (gp_cur + G3) : gp_cur;
        float girn = __ldg(gp_n);
        float gizn = __ldg(gp_n + HD);
        float ginn = __ldg(gp_n + 2 * HD);
        gp_cur = gp_n;

        // load h chunk (32 floats) — transposed layout, conflict-free
        ull h2[16];
        {
            const longlong2* hp = (const longlong2*)(hT + (cb << 9));
#pragma unroll
            for (int j = 0; j < 8; j++) {
                longlong2 qv = hp[(j << 4) + c4];
                h2[2 * j]     = (ull)qv.x;
                h2[2 * j + 1] = (ull)qv.y;
            }
        }
        float hold = hT[(cb << 9) + hoffb];

        // matvec: 6 groups, all from registers
        float accs[6];
#pragma unroll
        for (int g = 0; g < 6; g++) {
            ull a = 0ull;
#pragma unroll
            for (int k = 0; k < 16; k++) fma2(a, wreg[g][k], h2[k]);
            float2 u2 = upk2(a);
            accs[g] = u2.x + u2.y;
        }

        // xor butterfly levels 8,4,2
#pragma unroll
        for (int d = 8; d > 1; d >>= 1)
#pragma unroll
            for (int g = 0; g < 6; g++)
                accs[g] += __shfl_xor_sync(0xffffffffu, accs[g], d);

        // level 1 with partner-swap
        float v0 = b0 ? accs[0] : accs[1];
        float v1 = b0 ? accs[2] : accs[3];
        float v2 = b0 ? accs[4] : accs[5];
        float pr = (b0 ? accs[1] : accs[0]) + __shfl_xor_sync(0xffffffffu, v0, 1);
        float pz = (b0 ? accs[3] : accs[2]) + __shfl_xor_sync(0xffffffffu, v1, 1);
        float pn = (b0 ? accs[5] : accs[4]) + __shfl_xor_sync(0xffffffffu, v2, 1);

        float rg = fmaf(0.5f, tanh_fast(0.5f * (gir + pr + br)), 0.5f);
        float zg = fmaf(0.5f, tanh_fast(0.5f * (giz + pz + bz)), 0.5f);
        float ng = tanh_fast(fmaf(rg, pn + bn, gin));
        float hnew = fmaf(zg, hold - ng, ng);

        if (q == 0) g_hs[(size_t)t * HD + u_gbl] = hnew;

        // gather this lane's unit pair (canonical lanes: u0->0, u1->16, u2->1, u3->17)
        float hu_lo = __shfl_sync(0xffffffffu, hnew, p);        // unit 2p
        float hu_hi = __shfl_sync(0xffffffffu, hnew, 16 + p);   // unit 2p+1
        st_async_b64(rdata[nb], rbar[nb], pk2(hu_lo, hu_hi));

        gir = girn; giz = gizn; gin = ginn;

        unsigned par = nb ? (unsigned)ph1 : (unsigned)ph0;
        mbar_wait(smem_u32(&mbar[nb]), par);
        if (nb) ph1 ^= 1; else ph0 ^= 1;
    }
    cluster_sync_all();
}

// ---------------------------------------------------------------------------
// Attention pooling
// ---------------------------------------------------------------------------
__global__ void __launch_bounds__(128)
att_logits_kernel(const float* __restrict__ watt)
{
    int w = blockIdx.x * 4 + (threadIdx.x >> 5);
    int lane = threadIdx.x & 31;
    for (int i = 0; i < 8; i++) {
        int t = w * 8 + i;
        const float* hp = g_hs + (size_t)t * HD;
        float acc = 0.f;
#pragma unroll
        for (int k = 0; k < 16; k++)
            acc += hp[lane + (k << 5)] * watt[lane + (k << 5)];
        acc += __shfl_xor_sync(0xffffffffu, acc, 16);
        acc += __shfl_xor_sync(0xffffffffu, acc, 8);
        acc += __shfl_xor_sync(0xffffffffu, acc, 4);
        acc += __shfl_xor_sync(0xffffffffu, acc, 2);
        acc += __shfl_xor_sync(0xffffffffu, acc, 1);
        if (lane == 0) g_logits[t] = acc;
    }
}

__global__ void __launch_bounds__(1024)
att_softmax_kernel()
{
    __shared__ float red[1024];
    int tid = threadIdx.x;
    float l[4];
    float mx = -1e30f;
#pragma unroll
    for (int i = 0; i < 4; i++) {
        l[i] = g_logits[tid + (i << 10)];
        mx = fmaxf(mx, l[i]);
    }
    red[tid] = mx;
    __syncthreads();
    for (int s = 512; s > 0; s >>= 1) {
        if (tid < s) red[tid] = fmaxf(red[tid], red[tid + s]);
        __syncthreads();
    }
    mx = red[0];
    __syncthreads();
    float e[4];
    float se = 0.f;
#pragma unroll
    for (int i = 0; i < 4; i++) {
        e[i] = __expf(l[i] - mx);
        se += e[i];
    }
    red[tid] = se;
    __syncthreads();
    for (int s = 512; s > 0; s >>= 1) {
        if (tid < s) red[tid] += red[tid + s];
        __syncthreads();
    }
    float inv = 1.0f / red[0];
#pragma unroll
    for (int i = 0; i < 4; i++)
        g_alpha[tid + (i << 10)] = e[i] * inv;
}

__global__ void __launch_bounds__(512)
att_out_kernel()
{
    int b = blockIdx.x;
    int d = threadIdx.x;
    float acc = 0.f;
    for (int i = 0; i < 128; i++) {
        int t = b * 128 + i;
        acc += g_alpha[t] * g_hs[(size_t)t * HD + d];
    }
    g_part[b * HD + d] = acc;
}

__global__ void __launch_bounds__(512)
att_final_kernel(float* __restrict__ out)
{
    int d = threadIdx.x;
    float acc = 0.f;
#pragma unroll
    for (int b = 0; b < 32; b++)
        acc += g_part[b * HD + d];
    out[d] = acc;
}

// ---------------------------------------------------------------------------
// Launch — single stream (proven structure)
// ---------------------------------------------------------------------------
extern "C" void kernel_launch(void* const* d_in, const int* in_sizes, int n_in,
                              void* d_out, int out_size)
{
    const float* H    = (const float*)d_in[0];
    // d_in[1] = TE (unused by reference)
    const float* X    = (const float*)d_in[2];
    const float* Wih  = (const float*)d_in[3];
    const float* Whh  = (const float*)d_in[4];
    const float* bih  = (const float*)d_in[5];
    const float* bhh  = (const float*)d_in[6];
    const float* watt = (const float*)d_in[7];
    float* out = (float*)d_out;

    gemm1_kernel<<<dim3(32, 8), 256>>>(H, X);
    gemm2_kernel<<<dim3(32, 24), 256>>>(Wih, bih);

    cudaFuncSetAttribute(scan_kernel,
                         cudaFuncAttributeNonPortableClusterSizeAllowed, 1);

    cudaLaunchConfig_t cfg = {};
    cfg.gridDim = dim3(16, 1, 1);
    cfg.blockDim = dim3(SCAN_THREADS, 1, 1);
    cfg.dynamicSmemBytes = 0;
    cfg.stream = 0;
    cudaLaunchAttribute attr[1];
    attr[0].id = cudaLaunchAttributeClusterDimension;
    attr[0].val.clusterDim.x = 16;
    attr[0].val.clusterDim.y = 1;
    attr[0].val.clusterDim.z = 1;
    cfg.attrs = attr;
    cfg.numAttrs = 1;
    cudaLaunchKernelEx(&cfg, scan_kernel, Whh, bhh);

    att_logits_kernel<<<128, 128>>>(watt);
    att_softmax_kernel<<<1, 1024>>>();
    att_out_kernel<<<32, 512>>>();
    att_final_kernel<<<1, 512>>>(out);
}

// round 12
// speedup vs baseline: 1.6897x; 1.6897x over previous
#include <cuda_runtime.h>
#include <cuda_bf16.h>
#include <cstdint>
#include <cstddef>

// ---------------------------------------------------------------------------
// Problem constants
// ---------------------------------------------------------------------------
#define N_CODES 4880
#define T_STEPS 4096
#define VDIM    512
#define HD      512
#define G3      1536   // 3*HD

typedef unsigned long long ull;

// ---------------------------------------------------------------------------
// Scratch (device globals — no allocation allowed)
// ---------------------------------------------------------------------------
__device__ float g_visit[(size_t)T_STEPS * VDIM];     // 8 MB
__device__ float g_gi[(size_t)T_STEPS * G3];          // 24 MB
__device__ float g_hs[(size_t)T_STEPS * HD];          // 8 MB
__device__ float g_logits[T_STEPS];
__device__ float g_alpha[T_STEPS];
__device__ float g_part[32 * HD];

// ---------------------------------------------------------------------------
// Helpers
// ---------------------------------------------------------------------------
__device__ __forceinline__ unsigned smem_u32(const void* p) {
    unsigned a;
    asm("{ .reg .u64 t; cvta.to.shared.u64 t, %1; cvt.u32.u64 %0, t; }"
        : "=r"(a) : "l"(p));
    return a;
}
__device__ __forceinline__ unsigned mapa_u32(unsigned laddr, int rk) {
    unsigned r;
    asm("mapa.shared::cluster.u32 %0, %1, %2;" : "=r"(r) : "r"(laddr), "r"(rk));
    return r;
}
__device__ __forceinline__ ull pk2(float a, float b) {
    ull r; asm("mov.b64 %0, {%1, %2};" : "=l"(r) : "f"(a), "f"(b)); return r;
}
__device__ __forceinline__ ull pk2dup(float a) { return pk2(a, a); }
__device__ __forceinline__ void fma2(ull& d, ull a, ull b) {
    asm("fma.rn.f32x2 %0, %1, %2, %0;" : "+l"(d) : "l"(a), "l"(b));
}
__device__ __forceinline__ float2 upk2(ull v) {
    float2 r; asm("mov.b64 {%0, %1}, %2;" : "=f"(r.x), "=f"(r.y) : "l"(v));
    return r;
}
__device__ __forceinline__ float tanh_fast(float x) {
    float r; asm("tanh.approx.f32 %0, %1;" : "=f"(r) : "f"(x)); return r;
}
__device__ __forceinline__ void cluster_sync_all() {
    asm volatile("barrier.cluster.arrive.aligned;" ::: "memory");
    asm volatile("barrier.cluster.wait.aligned;" ::: "memory");
}
__device__ __forceinline__ void mbar_init(unsigned a, unsigned cnt) {
    asm volatile("mbarrier.init.shared.b64 [%0], %1;" :: "r"(a), "r"(cnt) : "memory");
}
__device__ __forceinline__ void mbar_expect(unsigned a, unsigned bytes) {
    asm volatile("mbarrier.arrive.expect_tx.shared.b64 _, [%0], %1;"
                 :: "r"(a), "r"(bytes) : "memory");
}
__device__ __forceinline__ void mbar_wait(unsigned a, unsigned parity) {
    asm volatile(
        "{\n\t.reg .pred P;\n\t"
        "LW_%=:\n\t"
        "mbarrier.try_wait.parity.acquire.cluster.shared::cta.b64 P, [%0], %1, 0x989680;\n\t"
        "@P bra.uni LD_%=;\n\t"
        "bra.uni LW_%=;\n\t"
        "LD_%=:\n\t}"
        :: "r"(a), "r"(parity) : "memory");
}
__device__ __forceinline__ void st_async_pre(unsigned ra, unsigned rb, unsigned val) {
    asm volatile(
        "st.async.shared::cluster.mbarrier::complete_tx::bytes.b32 [%0], %1, [%2];"
        :: "r"(ra), "r"(val), "r"(rb) : "memory");
}
__device__ __forceinline__ void cp_async16(unsigned dst, const void* src) {
    asm volatile("cp.async.cg.shared.global [%0], [%1], 16;"
                 :: "r"(dst), "l"(src) : "memory");
}
__device__ __forceinline__ void cp_commit() {
    asm volatile("cp.async.commit_group;" ::: "memory");
}
template <int N>
__device__ __forceinline__ void cp_wait() {
    asm volatile("cp.async.wait_group %0;" :: "n"(N) : "memory");
}

// ---------------------------------------------------------------------------
// GEMM1: visit[t][d] = sum_k H[k][t] * X[k][d]
//   128x64 tile, 256 threads, 8x4 per thread. cp.async DOUBLE-BUFFERED k-loop:
//   next tile's global loads overlap current tile's FMAs.
// ---------------------------------------------------------------------------
__global__ void __launch_bounds__(256)
gemm1_kernel(const float* __restrict__ H, const float* __restrict__ X)
{
    __shared__ float As[2][16 * 128];
    __shared__ float Bs[2][16 * 64];
    const int tid = threadIdx.x;
    const int t0 = blockIdx.x * 128;
    const int d0 = blockIdx.y * 64;
    const int tx = tid & 15;
    const int ty = tid >> 4;

    // per-thread staging coordinates
    const int a_kk0 = tid >> 5;              // j=0: kk 0..7
    const int a_tt4 = (tid & 31) << 2;
    const int b_kk  = tid >> 4;
    const int b_dd4 = (tid & 15) << 2;

    ull acc2[4][4];
#pragma unroll
    for (int mp = 0; mp < 4; mp++)
#pragma unroll
        for (int n = 0; n < 4; n++) acc2[mp][n] = 0ull;

    // stage tile kt into buffer buf
    auto stage = [&](int buf, int k0) {
#pragma unroll
        for (int j = 0; j < 2; j++) {
            int kk = a_kk0 + (j << 3);
            cp_async16(smem_u32(&As[buf][(kk << 7) + a_tt4]),
                       H + (size_t)(k0 + kk) * T_STEPS + t0 + a_tt4);
        }
        cp_async16(smem_u32(&Bs[buf][(b_kk << 6) + b_dd4]),
                   X + (size_t)(k0 + b_kk) * VDIM + d0 + b_dd4);
        cp_commit();
    };

    const int nk = N_CODES / 16;   // 305
    stage(0, 0);
    for (int kt = 0; kt < nk; kt++) {
        const int buf = kt & 1;
        if (kt + 1 < nk) {
            stage(buf ^ 1, (kt + 1) * 16);
            cp_wait<1>();
        } else {
            cp_wait<0>();
        }
        __syncthreads();
#pragma unroll
        for (int kk = 0; kk < 16; kk++) {
            const longlong2* ap = (const longlong2*)(&As[buf][(kk << 7) + (ty << 3)]);
            longlong2 a01 = ap[0];
            longlong2 a23 = ap[1];
            ull am[4] = {(ull)a01.x, (ull)a01.y, (ull)a23.x, (ull)a23.y};
            float4 b = *(const float4*)(&Bs[buf][(kk << 6) + (tx << 2)]);
            ull bd[4] = {pk2dup(b.x), pk2dup(b.y), pk2dup(b.z), pk2dup(b.w)};
#pragma unroll
            for (int mp = 0; mp < 4; mp++)
#pragma unroll
                for (int n = 0; n < 4; n++)
                    fma2(acc2[mp][n], am[mp], bd[n]);
        }
        __syncthreads();
    }
#pragma unroll
    for (int mp = 0; mp < 4; mp++) {
        float2 c0 = upk2(acc2[mp][0]);
        float2 c1 = upk2(acc2[mp][1]);
        float2 c2 = upk2(acc2[mp][2]);
        float2 c3 = upk2(acc2[mp][3]);
        size_t r0 = (size_t)(t0 + (ty << 3) + 2 * mp) * VDIM + d0 + (tx << 2);
        *(float4*)(g_visit + r0)        = make_float4(c0.x, c1.x, c2.x, c3.x);
        *(float4*)(g_visit + r0 + VDIM) = make_float4(c0.y, c1.y, c2.y, c3.y);
    }
}

// ---------------------------------------------------------------------------
// GEMM2: gi[t][g] = b_ih[g] + sum_d visit[t][d] * W_ih[g][d]  — R4 config
// ---------------------------------------------------------------------------
__global__ void __launch_bounds__(256)
gemm2_kernel(const float* __restrict__ Wih, const float* __restrict__ bih)
{
    __shared__ float As[16 * 128];
    __shared__ float Bs[16 * 64];
    const int tid = threadIdx.x;
    const int t0 = blockIdx.x * 128;
    const int g0 = blockIdx.y * 64;
    const int tx = tid & 15;
    const int ty = tid >> 4;

    ull acc2[4][4];
#pragma unroll
    for (int mp = 0; mp < 4; mp++)
#pragma unroll
        for (int n = 0; n < 4; n++) acc2[mp][n] = 0ull;

    for (int k0 = 0; k0 < VDIM; k0 += 16) {
#pragma unroll
        for (int j = 0; j < 2; j++) {
            int idx = tid + (j << 8);
            int tt  = idx >> 2;
            int kk  = (idx & 3) << 2;
            float4 v = *(const float4*)(g_visit + (size_t)(t0 + tt) * VDIM + k0 + kk);
            As[(kk + 0) * 128 + tt] = v.x;
            As[(kk + 1) * 128 + tt] = v.y;
            As[(kk + 2) * 128 + tt] = v.z;
            As[(kk + 3) * 128 + tt] = v.w;
        }
        {
            int gg = tid >> 2;
            int kk = (tid & 3) << 2;
            float4 v = *(const float4*)(Wih + (size_t)(g0 + gg) * VDIM + k0 + kk);
            Bs[(kk + 0) * 64 + gg] = v.x;
            Bs[(kk + 1) * 64 + gg] = v.y;
            Bs[(kk + 2) * 64 + gg] = v.z;
            Bs[(kk + 3) * 64 + gg] = v.w;
        }
        __syncthreads();
#pragma unroll
        for (int kk = 0; kk < 16; kk++) {
            const longlong2* ap = (const longlong2*)(As + (kk << 7) + (ty << 3));
            longlong2 a01 = ap[0];
            longlong2 a23 = ap[1];
            ull am[4] = {(ull)a01.x, (ull)a01.y, (ull)a23.x, (ull)a23.y};
            float4 b = *(const float4*)(Bs + (kk << 6) + (tx << 2));
            ull bd[4] = {pk2dup(b.x), pk2dup(b.y), pk2dup(b.z), pk2dup(b.w)};
#pragma unroll
            for (int mp = 0; mp < 4; mp++)
#pragma unroll
                for (int n = 0; n < 4; n++)
                    fma2(acc2[mp][n], am[mp], bd[n]);
        }
        __syncthreads();
    }
    float4 bv = *(const float4*)(bih + g0 + (tx << 2));
#pragma unroll
    for (int mp = 0; mp < 4; mp++) {
        float2 c0 = upk2(acc2[mp][0]);
        float2 c1 = upk2(acc2[mp][1]);
        float2 c2 = upk2(acc2[mp][2]);
        float2 c3 = upk2(acc2[mp][3]);
        size_t r0 = (size_t)(t0 + (ty << 3) + 2 * mp) * G3 + g0 + (tx << 2);
        *(float4*)(g_gi + r0)      = make_float4(c0.x + bv.x, c1.x + bv.y, c2.x + bv.z, c3.x + bv.w);
        *(float4*)(g_gi + r0 + G3) = make_float4(c0.y + bv.x, c1.y + bv.y, c2.y + bv.z, c3.y + bv.w);
    }
}

// ---------------------------------------------------------------------------
// GRU scan — EXACT R10 build (best validated): 16-CTA cluster, 256 threads,
// bar-free mbarrier/st.async loop, all 6 weight groups in registers, 2×b32
// fan-out per lane to distinct ranks (q mapping).
// ---------------------------------------------------------------------------
#define SCAN_THREADS 256

__global__ void __launch_bounds__(SCAN_THREADS, 1)
scan_kernel(const float* __restrict__ Whh, const float* __restrict__ bhh)
{
    __shared__ float  hT[2 * HD];         // transposed h, 2 buffers
    __shared__ ull    mbar[2];

    const int tid  = threadIdx.x;
    const int lane = tid & 31;
    const int w    = tid >> 5;
    const int cta  = blockIdx.x;          // cluster rank
    const int c4   = lane & 15;           // h-chunk (source CTA) index
    const int rh   = lane >> 4;

    const int ui    = ((lane & 1) << 1) | rh;
    const int q     = (lane >> 1) & 7;
    const int ul    = (w << 2) + ui;
    const int u_gbl = (cta << 5) + ul;

    // --- one-time weight staging: all 6 groups in registers ---
    ull wreg[6][16];
#pragma unroll
    for (int g = 0; g < 6; g++) {
        int grow = ((g >> 1) << 9) + (cta << 5) + (w << 2) + ((g & 1) << 1) + rh;
        const ull* src = (const ull*)(Whh + (size_t)grow * HD + (c4 << 5));
#pragma unroll
        for (int k = 0; k < 16; k++) wreg[g][k] = src[k];
    }
    const float br = bhh[u_gbl];
    const float bz = bhh[HD + u_gbl];
    const float bn = bhh[2 * HD + u_gbl];

    for (int i = tid; i < HD; i += SCAN_THREADS) hT[i] = 0.0f;
    if (tid == 0) { mbar_init(smem_u32(&mbar[0]), 1); mbar_init(smem_u32(&mbar[1]), 1); }
    __syncthreads();
    cluster_sync_all();

    // precompute remote addresses (2 ranks x 2 buffers)
    const int hoffb = ((ul >> 2) << 6) + (cta << 2) + (ul & 3);
    unsigned rdata[2][2], rbar[2][2];
#pragma unroll
    for (int b = 0; b < 2; b++) {
        unsigned ld = smem_u32(&hT[(b << 9) + hoffb]);
        unsigned lm = smem_u32(&mbar[b]);
#pragma unroll
        for (int r = 0; r < 2; r++) {
            rdata[b][r] = mapa_u32(ld, (q << 1) + r);
            rbar[b][r]  = mapa_u32(lm, (q << 1) + r);
        }
    }

    // gi preload for t=0; carried pointer
    const float* gp_cur = g_gi + u_gbl;
    float gir = __ldg(gp_cur);
    float giz = __ldg(gp_cur + HD);
    float gin = __ldg(gp_cur + 2 * HD);

    int ph0 = 0, ph1 = 0;
    const bool b0 = (lane & 1);
    for (int t = 0; t < T_STEPS; t++) {
        const int cb = t & 1;
        const int nb = cb ^ 1;

        if (tid == 0) mbar_expect(smem_u32(&mbar[nb]), 2048u);

        // prefetch gi for t+1 (carried pointer)
        const float* gp_n = (t + 1 < T_STEPS) ? (gp_cur + G3) : gp_cur;
        float girn = __ldg(gp_n);
        float gizn = __ldg(gp_n + HD);
        float ginn = __ldg(gp_n + 2 * HD);
        gp_cur = gp_n;

        // load h chunk (32 floats) — transposed layout, conflict-free
        ull h2[16];
        {
            const longlong2* hp = (const longlong2*)(hT + (cb << 9));
#pragma unroll
            for (int j = 0; j < 8; j++) {
                longlong2 qv = hp[(j << 4) + c4];
                h2[2 * j]     = (ull)qv.x;
                h2[2 * j + 1] = (ull)qv.y;
            }
        }
        float hold = hT[(cb << 9) + hoffb];

        // matvec: 6 groups, all from registers
        float accs[6];
#pragma unroll
        for (int g = 0; g < 6; g++) {
            ull a = 0ull;
#pragma unroll
            for (int k = 0; k < 16; k++) fma2(a, wreg[g][k], h2[k]);
            float2 u2 = upk2(a);
            accs[g] = u2.x + u2.y;
        }

        // xor butterfly levels 8,4,2
#pragma unroll
        for (int d = 8; d > 1; d >>= 1)
#pragma unroll
            for (int g = 0; g < 6; g++)
                accs[g] += __shfl_xor_sync(0xffffffffu, accs[g], d);

        // level 1 with partner-swap
        float v0 = b0 ? accs[0] : accs[1];
        float v1 = b0 ? accs[2] : accs[3];
        float v2 = b0 ? accs[4] : accs[5];
        float pr = (b0 ? accs[1] : accs[0]) + __shfl_xor_sync(0xffffffffu, v0, 1);
        float pz = (b0 ? accs[3] : accs[2]) + __shfl_xor_sync(0xffffffffu, v1, 1);
        float pn = (b0 ? accs[5] : accs[4]) + __shfl_xor_sync(0xffffffffu, v2, 1);

        float rg = fmaf(0.5f, tanh_fast(0.5f * (gir + pr + br)), 0.5f);
        float zg = fmaf(0.5f, tanh_fast(0.5f * (giz + pz + bz)), 0.5f);
        float ng = tanh_fast(fmaf(rg, pn + bn, gin));
        float hnew = fmaf(zg, hold - ng, ng);

        if (q == 0) g_hs[(size_t)t * HD + u_gbl] = hnew;

        unsigned hv = __float_as_uint(hnew);
        st_async_pre(rdata[nb][0], rbar[nb][0], hv);
        st_async_pre(rdata[nb][1], rbar[nb][1], hv);

        gir = girn; giz = gizn; gin = ginn;

        unsigned par = nb ? (unsigned)ph1 : (unsigned)ph0;
        mbar_wait(smem_u32(&mbar[nb]), par);
        if (nb) ph1 ^= 1; else ph0 ^= 1;
    }
    cluster_sync_all();
}

// ---------------------------------------------------------------------------
// Attention pooling
// ---------------------------------------------------------------------------
__global__ void __launch_bounds__(128)
att_logits_kernel(const float* __restrict__ watt)
{
    int w = blockIdx.x * 4 + (threadIdx.x >> 5);
    int lane = threadIdx.x & 31;
    for (int i = 0; i < 8; i++) {
        int t = w * 8 + i;
        const float* hp = g_hs + (size_t)t * HD;
        float acc = 0.f;
#pragma unroll
        for (int k = 0; k < 16; k++)
            acc += hp[lane + (k << 5)] * watt[lane + (k << 5)];
        acc += __shfl_xor_sync(0xffffffffu, acc, 16);
        acc += __shfl_xor_sync(0xffffffffu, acc, 8);
        acc += __shfl_xor_sync(0xffffffffu, acc, 4);
        acc += __shfl_xor_sync(0xffffffffu, acc, 2);
        acc += __shfl_xor_sync(0xffffffffu, acc, 1);
        if (lane == 0) g_logits[t] = acc;
    }
}

__global__ void __launch_bounds__(1024)
att_softmax_kernel()
{
    __shared__ float red[1024];
    int tid = threadIdx.x;
    float l[4];
    float mx = -1e30f;
#pragma unroll
    for (int i = 0; i < 4; i++) {
        l[i] = g_logits[tid + (i << 10)];
        mx = fmaxf(mx, l[i]);
    }
    red[tid] = mx;
    __syncthreads();
    for (int s = 512; s > 0; s >>= 1) {
        if (tid < s) red[tid] = fmaxf(red[tid], red[tid + s]);
        __syncthreads();
    }
    mx = red[0];
    __syncthreads();
    float e[4];
    float se = 0.f;
#pragma unroll
    for (int i = 0; i < 4; i++) {
        e[i] = __expf(l[i] - mx);
        se += e[i];
    }
    red[tid] = se;
    __syncthreads();
    for (int s = 512; s > 0; s >>= 1) {
        if (tid < s) red[tid] += red[tid + s];
        __syncthreads();
    }
    float inv = 1.0f / red[0];
#pragma unroll
    for (int i = 0; i < 4; i++)
        g_alpha[tid + (i << 10)] = e[i] * inv;
}

__global__ void __launch_bounds__(512)
att_out_kernel()
{
    int b = blockIdx.x;
    int d = threadIdx.x;
    float acc = 0.f;
    for (int i = 0; i < 128; i++) {
        int t = b * 128 + i;
        acc += g_alpha[t] * g_hs[(size_t)t * HD + d];
    }
    g_part[b * HD + d] = acc;
}

__global__ void __launch_bounds__(512)
att_final_kernel(float* __restrict__ out)
{
    int d = threadIdx.x;
    float acc = 0.f;
#pragma unroll
    for (int b = 0; b < 32; b++)
        acc += g_part[b * HD + d];
    out[d] = acc;
}

// ---------------------------------------------------------------------------
// Launch — single stream (proven structure)
// ---------------------------------------------------------------------------
extern "C" void kernel_launch(void* const* d_in, const int* in_sizes, int n_in,
                              void* d_out, int out_size)
{
    const float* H    = (const float*)d_in[0];
    // d_in[1] = TE (unused by reference)
    const float* X    = (const float*)d_in[2];
    const float* Wih  = (const float*)d_in[3];
    const float* Whh  = (const float*)d_in[4];
    const float* bih  = (const float*)d_in[5];
    const float* bhh  = (const float*)d_in[6];
    const float* watt = (const float*)d_in[7];
    float* out = (float*)d_out;

    gemm1_kernel<<<dim3(32, 8), 256>>>(H, X);
    gemm2_kernel<<<dim3(32, 24), 256>>>(Wih, bih);

    cudaFuncSetAttribute(scan_kernel,
                         cudaFuncAttributeNonPortableClusterSizeAllowed, 1);

    cudaLaunchConfig_t cfg = {};
    cfg.gridDim = dim3(16, 1, 1);
    cfg.blockDim = dim3(SCAN_THREADS, 1, 1);
    cfg.dynamicSmemBytes = 0;
    cfg.stream = 0;
    cudaLaunchAttribute attr[1];
    attr[0].id = cudaLaunchAttributeClusterDimension;
    attr[0].val.clusterDim.x = 16;
    attr[0].val.clusterDim.y = 1;
    attr[0].val.clusterDim.z = 1;
    cfg.attrs = attr;
    cfg.numAttrs = 1;
    cudaLaunchKernelEx(&cfg, scan_kernel, Whh, bhh);

    att_logits_kernel<<<128, 128>>>(watt);
    att_softmax_kernel<<<1, 1024>>>();
    att_out_kernel<<<32, 512>>>();
    att_final_kernel<<<1, 512>>>(out);
}

// round 13
// speedup vs baseline: 1.6976x; 1.0047x over previous
#include <cuda_runtime.h>
#include <cuda_bf16.h>
#include <cstdint>
#include <cstddef>

// ---------------------------------------------------------------------------
// Problem constants
// ---------------------------------------------------------------------------
#define N_CODES 4880
#define T_STEPS 4096
#define VDIM    512
#define HD      512
#define G3      1536   // 3*HD

typedef unsigned long long ull;

// ---------------------------------------------------------------------------
// Scratch (device globals — no allocation allowed)
// ---------------------------------------------------------------------------
__device__ float g_visit[(size_t)T_STEPS * VDIM];     // 8 MB
__device__ float g_gi[(size_t)T_STEPS * G3];          // 24 MB
__device__ float g_hs[(size_t)T_STEPS * HD];          // 8 MB
__device__ float g_logits[T_STEPS];
__device__ float g_alpha[T_STEPS];
__device__ float g_part[128 * HD];

// ---------------------------------------------------------------------------
// Helpers
// ---------------------------------------------------------------------------
__device__ __forceinline__ unsigned smem_u32(const void* p) {
    unsigned a;
    asm("{ .reg .u64 t; cvta.to.shared.u64 t, %1; cvt.u32.u64 %0, t; }"
        : "=r"(a) : "l"(p));
    return a;
}
__device__ __forceinline__ unsigned mapa_u32(unsigned laddr, int rk) {
    unsigned r;
    asm("mapa.shared::cluster.u32 %0, %1, %2;" : "=r"(r) : "r"(laddr), "r"(rk));
    return r;
}
__device__ __forceinline__ ull pk2(float a, float b) {
    ull r; asm("mov.b64 %0, {%1, %2};" : "=l"(r) : "f"(a), "f"(b)); return r;
}
__device__ __forceinline__ ull pk2dup(float a) { return pk2(a, a); }
__device__ __forceinline__ void fma2(ull& d, ull a, ull b) {
    asm("fma.rn.f32x2 %0, %1, %2, %0;" : "+l"(d) : "l"(a), "l"(b));
}
__device__ __forceinline__ float2 upk2(ull v) {
    float2 r; asm("mov.b64 {%0, %1}, %2;" : "=f"(r.x), "=f"(r.y) : "l"(v));
    return r;
}
__device__ __forceinline__ float tanh_fast(float x) {
    float r; asm("tanh.approx.f32 %0, %1;" : "=f"(r) : "f"(x)); return r;
}
__device__ __forceinline__ void cluster_sync_all() {
    asm volatile("barrier.cluster.arrive.aligned;" ::: "memory");
    asm volatile("barrier.cluster.wait.aligned;" ::: "memory");
}
__device__ __forceinline__ void mbar_init(unsigned a, unsigned cnt) {
    asm volatile("mbarrier.init.shared.b64 [%0], %1;" :: "r"(a), "r"(cnt) : "memory");
}
__device__ __forceinline__ void mbar_expect(unsigned a, unsigned bytes) {
    asm volatile("mbarrier.arrive.expect_tx.shared.b64 _, [%0], %1;"
                 :: "r"(a), "r"(bytes) : "memory");
}
__device__ __forceinline__ void mbar_wait(unsigned a, unsigned parity) {
    asm volatile(
        "{\n\t.reg .pred P;\n\t"
        "LW_%=:\n\t"
        "mbarrier.try_wait.parity.acquire.cluster.shared::cta.b64 P, [%0], %1, 0x989680;\n\t"
        "@P bra.uni LD_%=;\n\t"
        "bra.uni LW_%=;\n\t"
        "LD_%=:\n\t}"
        :: "r"(a), "r"(parity) : "memory");
}
__device__ __forceinline__ void st_async_pre(unsigned ra, unsigned rb, unsigned val) {
    asm volatile(
        "st.async.shared::cluster.mbarrier::complete_tx::bytes.b32 [%0], %1, [%2];"
        :: "r"(ra), "r"(val), "r"(rb) : "memory");
}
__device__ __forceinline__ void cp_async16(unsigned dst, const void* src) {
    asm volatile("cp.async.cg.shared.global [%0], [%1], 16;"
                 :: "r"(dst), "l"(src) : "memory");
}
__device__ __forceinline__ void cp_commit() {
    asm volatile("cp.async.commit_group;" ::: "memory");
}
template <int N>
__device__ __forceinline__ void cp_wait() {
    asm volatile("cp.async.wait_group %0;" :: "n"(N) : "memory");
}

// ---------------------------------------------------------------------------
// GEMM1: visit[t][d] = sum_k H[k][t] * X[k][d]
//   128x64 tile, 256 threads, 8x4 per thread. cp.async double-buffered k-loop.
// ---------------------------------------------------------------------------
__global__ void __launch_bounds__(256)
gemm1_kernel(const float* __restrict__ H, const float* __restrict__ X)
{
    __shared__ float As[2][16 * 128];
    __shared__ float Bs[2][16 * 64];
    const int tid = threadIdx.x;
    const int t0 = blockIdx.x * 128;
    const int d0 = blockIdx.y * 64;
    const int tx = tid & 15;
    const int ty = tid >> 4;

    const int a_kk0 = tid >> 5;
    const int a_tt4 = (tid & 31) << 2;
    const int b_kk  = tid >> 4;
    const int b_dd4 = (tid & 15) << 2;

    ull acc2[4][4];
#pragma unroll
    for (int mp = 0; mp < 4; mp++)
#pragma unroll
        for (int n = 0; n < 4; n++) acc2[mp][n] = 0ull;

    auto stage = [&](int buf, int k0) {
#pragma unroll
        for (int j = 0; j < 2; j++) {
            int kk = a_kk0 + (j << 3);
            cp_async16(smem_u32(&As[buf][(kk << 7) + a_tt4]),
                       H + (size_t)(k0 + kk) * T_STEPS + t0 + a_tt4);
        }
        cp_async16(smem_u32(&Bs[buf][(b_kk << 6) + b_dd4]),
                   X + (size_t)(k0 + b_kk) * VDIM + d0 + b_dd4);
        cp_commit();
    };

    const int nk = N_CODES / 16;   // 305
    stage(0, 0);
    for (int kt = 0; kt < nk; kt++) {
        const int buf = kt & 1;
        if (kt + 1 < nk) {
            stage(buf ^ 1, (kt + 1) * 16);
            cp_wait<1>();
        } else {
            cp_wait<0>();
        }
        __syncthreads();
#pragma unroll
        for (int kk = 0; kk < 16; kk++) {
            const longlong2* ap = (const longlong2*)(&As[buf][(kk << 7) + (ty << 3)]);
            longlong2 a01 = ap[0];
            longlong2 a23 = ap[1];
            ull am[4] = {(ull)a01.x, (ull)a01.y, (ull)a23.x, (ull)a23.y};
            float4 b = *(const float4*)(&Bs[buf][(kk << 6) + (tx << 2)]);
            ull bd[4] = {pk2dup(b.x), pk2dup(b.y), pk2dup(b.z), pk2dup(b.w)};
#pragma unroll
            for (int mp = 0; mp < 4; mp++)
#pragma unroll
                for (int n = 0; n < 4; n++)
                    fma2(acc2[mp][n], am[mp], bd[n]);
        }
        __syncthreads();
    }
#pragma unroll
    for (int mp = 0; mp < 4; mp++) {
        float2 c0 = upk2(acc2[mp][0]);
        float2 c1 = upk2(acc2[mp][1]);
        float2 c2 = upk2(acc2[mp][2]);
        float2 c3 = upk2(acc2[mp][3]);
        size_t r0 = (size_t)(t0 + (ty << 3) + 2 * mp) * VDIM + d0 + (tx << 2);
        *(float4*)(g_visit + r0)        = make_float4(c0.x, c1.x, c2.x, c3.x);
        *(float4*)(g_visit + r0 + VDIM) = make_float4(c0.y, c1.y, c2.y, c3.y);
    }
}

// ---------------------------------------------------------------------------
// GEMM2: gi[t][g] = b_ih[g] + sum_d visit[t][d] * W_ih[g][d]
//   Register-staged double buffer: next k-tile loaded into regs while the
//   current tile computes. Identical arithmetic to the plain version.
// ---------------------------------------------------------------------------
__global__ void __launch_bounds__(256)
gemm2_kernel(const float* __restrict__ Wih, const float* __restrict__ bih)
{
    __shared__ float As[16 * 128];
    __shared__ float Bs[16 * 64];
    const int tid = threadIdx.x;
    const int t0 = blockIdx.x * 128;
    const int g0 = blockIdx.y * 64;
    const int tx = tid & 15;
    const int ty = tid >> 4;

    // staging coordinates
    const int s_tt0 = tid >> 2;               // j=0 row
    const int s_kk  = (tid & 3) << 2;
    const int s_gg  = tid >> 2;

    ull acc2[4][4];
#pragma unroll
    for (int mp = 0; mp < 4; mp++)
#pragma unroll
        for (int n = 0; n < 4; n++) acc2[mp][n] = 0ull;

    float4 ra0, ra1, rbv;
    auto load_tile = [&](int k0) {
        ra0 = *(const float4*)(g_visit + (size_t)(t0 + s_tt0) * VDIM + k0 + s_kk);
        ra1 = *(const float4*)(g_visit + (size_t)(t0 + s_tt0 + 64) * VDIM + k0 + s_kk);
        rbv = *(const float4*)(Wih + (size_t)(g0 + s_gg) * VDIM + k0 + s_kk);
    };
    auto store_tile = [&]() {
        As[(s_kk + 0) * 128 + s_tt0] = ra0.x;
        As[(s_kk + 1) * 128 + s_tt0] = ra0.y;
        As[(s_kk + 2) * 128 + s_tt0] = ra0.z;
        As[(s_kk + 3) * 128 + s_tt0] = ra0.w;
        As[(s_kk + 0) * 128 + s_tt0 + 64] = ra1.x;
        As[(s_kk + 1) * 128 + s_tt0 + 64] = ra1.y;
        As[(s_kk + 2) * 128 + s_tt0 + 64] = ra1.z;
        As[(s_kk + 3) * 128 + s_tt0 + 64] = ra1.w;
        Bs[(s_kk + 0) * 64 + s_gg] = rbv.x;
        Bs[(s_kk + 1) * 64 + s_gg] = rbv.y;
        Bs[(s_kk + 2) * 64 + s_gg] = rbv.z;
        Bs[(s_kk + 3) * 64 + s_gg] = rbv.w;
    };

    load_tile(0);
    for (int k0 = 0; k0 < VDIM; k0 += 16) {
        store_tile();
        __syncthreads();
        if (k0 + 16 < VDIM) load_tile(k0 + 16);   // in flight during compute
#pragma unroll
        for (int kk = 0; kk < 16; kk++) {
            const longlong2* ap = (const longlong2*)(As + (kk << 7) + (ty << 3));
            longlong2 a01 = ap[0];
            longlong2 a23 = ap[1];
            ull am[4] = {(ull)a01.x, (ull)a01.y, (ull)a23.x, (ull)a23.y};
            float4 b = *(const float4*)(Bs + (kk << 6) + (tx << 2));
            ull bd[4] = {pk2dup(b.x), pk2dup(b.y), pk2dup(b.z), pk2dup(b.w)};
#pragma unroll
            for (int mp = 0; mp < 4; mp++)
#pragma unroll
                for (int n = 0; n < 4; n++)
                    fma2(acc2[mp][n], am[mp], bd[n]);
        }
        __syncthreads();
    }
    float4 bv = *(const float4*)(bih + g0 + (tx << 2));
#pragma unroll
    for (int mp = 0; mp < 4; mp++) {
        float2 c0 = upk2(acc2[mp][0]);
        float2 c1 = upk2(acc2[mp][1]);
        float2 c2 = upk2(acc2[mp][2]);
        float2 c3 = upk2(acc2[mp][3]);
        size_t r0 = (size_t)(t0 + (ty << 3) + 2 * mp) * G3 + g0 + (tx << 2);
        *(float4*)(g_gi + r0)      = make_float4(c0.x + bv.x, c1.x + bv.y, c2.x + bv.z, c3.x + bv.w);
        *(float4*)(g_gi + r0 + G3) = make_float4(c0.y + bv.x, c1.y + bv.y, c2.y + bv.z, c3.y + bv.w);
    }
}

// ---------------------------------------------------------------------------
// GRU scan — frozen R10 build (best validated).
// ---------------------------------------------------------------------------
#define SCAN_THREADS 256

__global__ void __launch_bounds__(SCAN_THREADS, 1)
scan_kernel(const float* __restrict__ Whh, const float* __restrict__ bhh)
{
    __shared__ float  hT[2 * HD];
    __shared__ ull    mbar[2];

    const int tid  = threadIdx.x;
    const int lane = tid & 31;
    const int w    = tid >> 5;
    const int cta  = blockIdx.x;
    const int c4   = lane & 15;
    const int rh   = lane >> 4;

    const int ui    = ((lane & 1) << 1) | rh;
    const int q     = (lane >> 1) & 7;
    const int ul    = (w << 2) + ui;
    const int u_gbl = (cta << 5) + ul;

    ull wreg[6][16];
#pragma unroll
    for (int g = 0; g < 6; g++) {
        int grow = ((g >> 1) << 9) + (cta << 5) + (w << 2) + ((g & 1) << 1) + rh;
        const ull* src = (const ull*)(Whh + (size_t)grow * HD + (c4 << 5));
#pragma unroll
        for (int k = 0; k < 16; k++) wreg[g][k] = src[k];
    }
    const float br = bhh[u_gbl];
    const float bz = bhh[HD + u_gbl];
    const float bn = bhh[2 * HD + u_gbl];

    for (int i = tid; i < HD; i += SCAN_THREADS) hT[i] = 0.0f;
    if (tid == 0) { mbar_init(smem_u32(&mbar[0]), 1); mbar_init(smem_u32(&mbar[1]), 1); }
    __syncthreads();
    cluster_sync_all();

    const int hoffb = ((ul >> 2) << 6) + (cta << 2) + (ul & 3);
    unsigned rdata[2][2], rbar[2][2];
#pragma unroll
    for (int b = 0; b < 2; b++) {
        unsigned ld = smem_u32(&hT[(b << 9) + hoffb]);
        unsigned lm = smem_u32(&mbar[b]);
#pragma unroll
        for (int r = 0; r < 2; r++) {
            rdata[b][r] = mapa_u32(ld, (q << 1) + r);
            rbar[b][r]  = mapa_u32(lm, (q << 1) + r);
        }
    }

    const float* gp_cur = g_gi + u_gbl;
    float gir = __ldg(gp_cur);
    float giz = __ldg(gp_cur + HD);
    float gin = __ldg(gp_cur + 2 * HD);

    int ph0 = 0, ph1 = 0;
    const bool b0 = (lane & 1);
    for (int t = 0; t < T_STEPS; t++) {
        const int cb = t & 1;
        const int nb = cb ^ 1;

        if (tid == 0) mbar_expect(smem_u32(&mbar[nb]), 2048u);

        const float* gp_n = (t + 1 < T_STEPS) ? (gp_cur + G3) : gp_cur;
        float girn = __ldg(gp_n);
        float gizn = __ldg(gp_n + HD);
        float ginn = __ldg(gp_n + 2 * HD);
        gp_cur = gp_n;

        ull h2[16];
        {
            const longlong2* hp = (const longlong2*)(hT + (cb << 9));
#pragma unroll
            for (int j = 0; j < 8; j++) {
                longlong2 qv = hp[(j << 4) + c4];
                h2[2 * j]     = (ull)qv.x;
                h2[2 * j + 1] = (ull)qv.y;
            }
        }
        float hold = hT[(cb << 9) + hoffb];

        float accs[6];
#pragma unroll
        for (int g = 0; g < 6; g++) {
            ull a = 0ull;
#pragma unroll
            for (int k = 0; k < 16; k++) fma2(a, wreg[g][k], h2[k]);
            float2 u2 = upk2(a);
            accs[g] = u2.x + u2.y;
        }

#pragma unroll
        for (int d = 8; d > 1; d >>= 1)
#pragma unroll
            for (int g = 0; g < 6; g++)
                accs[g] += __shfl_xor_sync(0xffffffffu, accs[g], d);

        float v0 = b0 ? accs[0] : accs[1];
        float v1 = b0 ? accs[2] : accs[3];
        float v2 = b0 ? accs[4] : accs[5];
        float pr = (b0 ? accs[1] : accs[0]) + __shfl_xor_sync(0xffffffffu, v0, 1);
        float pz = (b0 ? accs[3] : accs[2]) + __shfl_xor_sync(0xffffffffu, v1, 1);
        float pn = (b0 ? accs[5] : accs[4]) + __shfl_xor_sync(0xffffffffu, v2, 1);

        float rg = fmaf(0.5f, tanh_fast(0.5f * (gir + pr + br)), 0.5f);
        float zg = fmaf(0.5f, tanh_fast(0.5f * (giz + pz + bz)), 0.5f);
        float ng = tanh_fast(fmaf(rg, pn + bn, gin));
        float hnew = fmaf(zg, hold - ng, ng);

        if (q == 0) g_hs[(size_t)t * HD + u_gbl] = hnew;

        unsigned hv = __float_as_uint(hnew);
        st_async_pre(rdata[nb][0], rbar[nb][0], hv);
        st_async_pre(rdata[nb][1], rbar[nb][1], hv);

        gir = girn; giz = gizn; gin = ginn;

        unsigned par = nb ? (unsigned)ph1 : (unsigned)ph0;
        mbar_wait(smem_u32(&mbar[nb]), par);
        if (nb) ph1 ^= 1; else ph0 ^= 1;
    }
    cluster_sync_all();
}

// ---------------------------------------------------------------------------
// Attention pooling — high-occupancy versions
// ---------------------------------------------------------------------------
__global__ void __launch_bounds__(256)
att_logits_kernel(const float* __restrict__ watt)
{
    // one warp per timestep: grid 512 x 8 warps = 4096 warps
    int t = blockIdx.x * 8 + (threadIdx.x >> 5);
    int lane = threadIdx.x & 31;
    const float4* hp = (const float4*)(g_hs + (size_t)t * HD);
    const float4* wp = (const float4*)watt;
    float acc = 0.f;
#pragma unroll
    for (int j = 0; j < 4; j++) {
        float4 h4 = __ldg(hp + lane + (j << 5));
        float4 w4 = __ldg(wp + lane + (j << 5));
        acc += h4.x * w4.x + h4.y * w4.y + h4.z * w4.z + h4.w * w4.w;
    }
    acc += __shfl_xor_sync(0xffffffffu, acc, 16);
    acc += __shfl_xor_sync(0xffffffffu, acc, 8);
    acc += __shfl_xor_sync(0xffffffffu, acc, 4);
    acc += __shfl_xor_sync(0xffffffffu, acc, 2);
    acc += __shfl_xor_sync(0xffffffffu, acc, 1);
    if (lane == 0) g_logits[t] = acc;
}

__global__ void __launch_bounds__(1024)
att_softmax_kernel()
{
    __shared__ float red[1024];
    int tid = threadIdx.x;
    float l[4];
    float mx = -1e30f;
#pragma unroll
    for (int i = 0; i < 4; i++) {
        l[i] = g_logits[tid + (i << 10)];
        mx = fmaxf(mx, l[i]);
    }
    red[tid] = mx;
    __syncthreads();
    for (int s = 512; s > 0; s >>= 1) {
        if (tid < s) red[tid] = fmaxf(red[tid], red[tid + s]);
        __syncthreads();
    }
    mx = red[0];
    __syncthreads();
    float e[4];
    float se = 0.f;
#pragma unroll
    for (int i = 0; i < 4; i++) {
        e[i] = __expf(l[i] - mx);
        se += e[i];
    }
    red[tid] = se;
    __syncthreads();
    for (int s = 512; s > 0; s >>= 1) {
        if (tid < s) red[tid] += red[tid + s];
        __syncthreads();
    }
    float inv = 1.0f / red[0];
#pragma unroll
    for (int i = 0; i < 4; i++)
        g_alpha[tid + (i << 10)] = e[i] * inv;
}

__global__ void __launch_bounds__(512)
att_out_kernel()
{
    // 128 blocks x 32 timesteps each
    int b = blockIdx.x;
    int d = threadIdx.x;
    float acc = 0.f;
#pragma unroll 4
    for (int i = 0; i < 32; i++) {
        int t = b * 32 + i;
        acc += g_alpha[t] * g_hs[(size_t)t * HD + d];
    }
    g_part[b * HD + d] = acc;
}

__global__ void __launch_bounds__(512)
att_final_kernel(float* __restrict__ out)
{
    int d = threadIdx.x;
    float acc = 0.f;
#pragma unroll
    for (int b = 0; b < 128; b++)
        acc += g_part[b * HD + d];
    out[d] = acc;
}

// ---------------------------------------------------------------------------
// Launch — single stream (proven structure)
// ---------------------------------------------------------------------------
extern "C" void kernel_launch(void* const* d_in, const int* in_sizes, int n_in,
                              void* d_out, int out_size)
{
    const float* H    = (const float*)d_in[0];
    // d_in[1] = TE (unused by reference)
    const float* X    = (const float*)d_in[2];
    const float* Wih  = (const float*)d_in[3];
    const float* Whh  = (const float*)d_in[4];
    const float* bih  = (const float*)d_in[5];
    const float* bhh  = (const float*)d_in[6];
    const float* watt = (const float*)d_in[7];
    float* out = (float*)d_out;

    gemm1_kernel<<<dim3(32, 8), 256>>>(H, X);
    gemm2_kernel<<<dim3(32, 24), 256>>>(Wih, bih);

    cudaFuncSetAttribute(scan_kernel,
                         cudaFuncAttributeNonPortableClusterSizeAllowed, 1);

    cudaLaunchConfig_t cfg = {};
    cfg.gridDim = dim3(16, 1, 1);
    cfg.blockDim = dim3(SCAN_THREADS, 1, 1);
    cfg.dynamicSmemBytes = 0;
    cfg.stream = 0;
    cudaLaunchAttribute attr[1];
    attr[0].id = cudaLaunchAttributeClusterDimension;
    attr[0].val.clusterDim.x = 16;
    attr[0].val.clusterDim.y = 1;
    attr[0].val.clusterDim.z = 1;
    cfg.attrs = attr;
    cfg.numAttrs = 1;
    cudaLaunchKernelEx(&cfg, scan_kernel, Whh, bhh);

    att_logits_kernel<<<512, 256>>>(watt);
    att_softmax_kernel<<<1, 1024>>>();
    att_out_kernel<<<128, 512>>>();
    att_final_kernel<<<1, 512>>>(out);
}